// round 2
// baseline (speedup 1.0000x reference)
#include <cuda_runtime.h>
#include <math.h>

#define BB 2
#define SS 2048
#define CQ 256
#define CC 256
#define DD 50
#define KK 101
#define PP 100
#define TS 16   // s-positions per CTA in kernel 1

// scratch: U[b,s,:] = W_a^T c_t[b,s]  and predicted centers p[b,s]
__device__ float g_U[BB * SS * CQ];
__device__ float g_p[BB * SS];

// ---------------------------------------------------------------------------
// Kernel 1: per 16-row tile of (b,s):
//   U[bs, j] = sum_c W_a[c, j] * c_t[bs, c]
//   p[bs]    = S * sigmoid( V_p . tanh(W_p @ c_t[bs]) )
// ---------------------------------------------------------------------------
__global__ void __launch_bounds__(256) k1_proj(const float* __restrict__ c_t,
                                               const float* __restrict__ W_a,
                                               const float* __restrict__ W_p,
                                               const float* __restrict__ V_p) {
    __shared__ float sc[TS][CC];      // c_t tile
    __shared__ float hv[TS][128];     // tanh(h_j)*V_p[j] per row (j<100, rest 0)

    const int bs0 = blockIdx.x * TS;
    const int tid = threadIdx.x;
    const int warp = tid >> 5, lane = tid & 31;

    // load c_t tile (coalesced)
    #pragma unroll
    for (int r = 0; r < TS; r++)
        sc[r][tid] = c_t[(size_t)(bs0 + r) * CC + tid];
    // zero hv
    for (int i = tid; i < TS * 128; i += 256)
        (&hv[0][0])[i] = 0.0f;
    __syncthreads();

    // ---- U: thread tid owns output column j = tid for all TS rows ----
    float acc[TS];
    #pragma unroll
    for (int r = 0; r < TS; r++) acc[r] = 0.0f;
    for (int c = 0; c < CC; c++) {
        float wa = W_a[c * CQ + tid];          // coalesced across threads
        #pragma unroll
        for (int r = 0; r < TS; r++)
            acc[r] = fmaf(wa, sc[r][c], acc[r]);   // sc[r][c] broadcast
    }
    #pragma unroll
    for (int r = 0; r < TS; r++)
        g_U[(size_t)(bs0 + r) * CQ + tid] = acc[r];

    // ---- p: warp handles hidden unit j; lanes stride the 256-dim dot ----
    for (int j = warp; j < PP; j += 8) {
        float wp[8];
        #pragma unroll
        for (int i = 0; i < 8; i++)
            wp[i] = W_p[j * CC + lane + 32 * i];   // coalesced
        const float vj = V_p[j];
        #pragma unroll 1
        for (int r = 0; r < TS; r++) {
            float d = 0.0f;
            #pragma unroll
            for (int i = 0; i < 8; i++)
                d = fmaf(wp[i], sc[r][lane + 32 * i], d);
            #pragma unroll
            for (int o = 16; o > 0; o >>= 1)
                d += __shfl_down_sync(0xffffffffu, d, o);
            if (lane == 0) hv[r][j] = tanhf(d) * vj;
        }
    }
    __syncthreads();

    // reduce 100 (padded 128) terms per row -> p
    for (int r = warp; r < TS; r += 8) {
        float v = 0.0f;
        #pragma unroll
        for (int t = 0; t < 4; t++)
            v += hv[r][lane + 32 * t];
        #pragma unroll
        for (int o = 16; o > 0; o >>= 1)
            v += __shfl_down_sync(0xffffffffu, v, o);
        if (lane == 0)
            g_p[bs0 + r] = (float)SS / (1.0f + expf(-v));
    }
}

// ---------------------------------------------------------------------------
// Kernel 2: one CTA per (b,s).
//   pass 1: a[k] = q1[k] . u     (warp-per-k dot, 256 wide)
//   softmax over K + gaussian decay -> weights w[k]
//   pass 2: s_t[c] = sum_k w[k] * q1[k][c]   (thread-per-c, coalesced)
// ---------------------------------------------------------------------------
__global__ void __launch_bounds__(256) k2_attn(const float* __restrict__ q,
                                               float* __restrict__ out) {
    __shared__ float su[CQ];
    __shared__ int   sidx[KK];   // 0 == invalid slot, else q-row + 1
    __shared__ float sa[KK];
    __shared__ float sw[KK];
    __shared__ float sp;

    const int bs = blockIdx.x;
    const int b = bs / SS;
    const int tid = threadIdx.x;
    const int warp = tid >> 5, lane = tid & 31;

    su[tid] = g_U[(size_t)bs * CQ + tid];
    if (tid == 0) sp = g_p[bs];
    __syncthreads();
    const float p = sp;

    // window indices (matches torch: trunc toward zero, clamp, mod S+1)
    if (tid < KK) {
        float raw = (p + (float)(tid - DD)) + 1.0f;
        int idx = (int)truncf(raw);
        if (idx < 0) idx = 0;
        if (idx > SS + 1) idx = SS + 1;
        idx = idx % (SS + 1);
        sidx[tid] = idx;
    }
    __syncthreads();

    const float* qb = q + (size_t)b * SS * CQ;

    // pass 1: scores
    for (int k = warp; k < KK; k += 8) {
        const int idx = sidx[k];
        float d = -INFINITY;
        if (idx != 0) {
            const float* qr = qb + (size_t)(idx - 1) * CQ;
            d = 0.0f;
            #pragma unroll
            for (int i = 0; i < 8; i++)
                d = fmaf(qr[lane + 32 * i], su[lane + 32 * i], d);
            #pragma unroll
            for (int o = 16; o > 0; o >>= 1)
                d += __shfl_down_sync(0xffffffffu, d, o);
        }
        if (lane == 0) sa[k] = d;
    }
    __syncthreads();

    // softmax + gaussian decay (warp 0, 4 slots per lane)
    if (warp == 0) {
        const float tp = truncf(p);
        float vals[4];
        float m = -INFINITY;
        #pragma unroll
        for (int t = 0; t < 4; t++) {
            int k = lane + 32 * t;
            vals[t] = (k < KK) ? sa[k] : -INFINITY;
            m = fmaxf(m, vals[t]);
        }
        #pragma unroll
        for (int o = 16; o > 0; o >>= 1)
            m = fmaxf(m, __shfl_xor_sync(0xffffffffu, m, o));
        float e[4];
        float ssum = 0.0f;
        #pragma unroll
        for (int t = 0; t < 4; t++) {
            e[t] = (vals[t] == -INFINITY) ? 0.0f : expf(vals[t] - m);
            ssum += e[t];
        }
        #pragma unroll
        for (int o = 16; o > 0; o >>= 1)
            ssum += __shfl_xor_sync(0xffffffffu, ssum, o);
        const float inv = 1.0f / ssum;
        #pragma unroll
        for (int t = 0; t < 4; t++) {
            int k = lane + 32 * t;
            if (k < KK) {
                float dd = ((float)(k - DD) + tp - p) * (1.0f / (float)DD);
                sw[k] = e[t] * inv * expf(-2.0f * dd * dd);
            }
        }
    }
    __syncthreads();

    // pass 2: weighted accumulation, thread-per-channel
    float accv = 0.0f;
    #pragma unroll 4
    for (int k = 0; k < KK; k++) {
        const int idx = sidx[k];
        if (idx > 0)
            accv = fmaf(sw[k], qb[(size_t)(idx - 1) * CQ + tid], accv);
    }
    out[(size_t)bs * CQ + tid] = accv;
}

extern "C" void kernel_launch(void* const* d_in, const int* in_sizes, int n_in,
                              void* d_out, int out_size) {
    const float* q   = (const float*)d_in[0];
    const float* c_t = (const float*)d_in[1];
    const float* W_a = (const float*)d_in[2];
    const float* W_p = (const float*)d_in[3];
    const float* V_p = (const float*)d_in[4];
    float* out = (float*)d_out;

    k1_proj<<<(BB * SS) / TS, 256>>>(c_t, W_a, W_p, V_p);
    k2_attn<<<BB * SS, 256>>>(q, out);
}

// round 6
// speedup vs baseline: 1.4887x; 1.4887x over previous
#include <cuda_runtime.h>
#include <math.h>

#define BB 2
#define SS 2048
#define CQ 256
#define CC 256
#define DD 50
#define KK 101
#define PP 100

// scratch: U[b,s,:] = W_a^T c_t[b,s]  and predicted centers p[b,s]
__device__ float g_U[BB * SS * CQ];
__device__ float g_p[BB * SS];

// ---------------------------------------------------------------------------
// Kernel P: predicted centers.  p[bs] = S * sigmoid( V_p . tanh(W_p @ c_t[bs]) )
// W_p staged in SMEM (pitch 257 -> conflict-free lane-per-j reads).
// Warp handles 4 rows; lane owns hidden units {lane, lane+32, lane+64, lane+96}.
// Register accumulators; one shfl-reduce per row.
// ---------------------------------------------------------------------------
#define PR 32   // rows per CTA
__global__ void __launch_bounds__(256) k_p(const float* __restrict__ c_t,
                                           const float* __restrict__ W_p,
                                           const float* __restrict__ V_p) {
    extern __shared__ float sm[];
    float* sWp = sm;                   // [PP][257]
    float* sc  = sm + PP * 257;        // [PR][256]

    const int tid = threadIdx.x, lane = tid & 31, warp = tid >> 5;
    const int r0 = blockIdx.x * PR;

    // stage W_p (coalesced read, conflict-free store)
    for (int i = tid; i < PP * CC; i += 256) {
        int j = i >> 8, c = i & 255;
        sWp[j * 257 + c] = W_p[i];
    }
    // stage c_t rows
    for (int i = tid; i < PR * CC; i += 256)
        sc[i] = c_t[(size_t)r0 * CC + i];
    __syncthreads();

    // V_p per lane-slot (0 for padded j)
    float vp[4];
    int   jj[4];
    #pragma unroll
    for (int g = 0; g < 4; g++) {
        int j = lane + 32 * g;
        jj[g] = (j < PP) ? j : PP - 1;
        vp[g] = (j < PP) ? V_p[j] : 0.0f;
    }

    float acc[4][4];   // [row][slot]
    #pragma unroll
    for (int r = 0; r < 4; r++)
        #pragma unroll
        for (int g = 0; g < 4; g++) acc[r][g] = 0.0f;

    const float* scw = sc + (warp * 4) * 256;
    for (int c0 = 0; c0 < CC; c0 += 4) {
        float4 s[4];
        #pragma unroll
        for (int r = 0; r < 4; r++)
            s[r] = *(const float4*)(scw + r * 256 + c0);   // broadcast LDS.128
        #pragma unroll
        for (int g = 0; g < 4; g++) {
            const float* wr = sWp + jj[g] * 257 + c0;      // conflict-free (257 % 32 == 1)
            float w0 = wr[0], w1 = wr[1], w2 = wr[2], w3 = wr[3];
            #pragma unroll
            for (int r = 0; r < 4; r++)
                acc[r][g] += w0 * s[r].x + w1 * s[r].y + w2 * s[r].z + w3 * s[r].w;
        }
    }

    #pragma unroll
    for (int r = 0; r < 4; r++) {
        float t = 0.0f;
        #pragma unroll
        for (int g = 0; g < 4; g++)
            t += tanhf(acc[r][g]) * vp[g];
        #pragma unroll
        for (int o = 16; o > 0; o >>= 1)
            t += __shfl_down_sync(0xffffffffu, t, o);
        if (lane == 0)
            g_p[r0 + warp * 4 + r] = (float)SS / (1.0f + expf(-t));
    }
}

// ---------------------------------------------------------------------------
// Kernel U: U[bs, j] = sum_c W_a[c, j] * c_t[bs, c]   (thread owns column j)
// float4 broadcast LDS of the c_t tile + W_a prefetch pipeline.
// ---------------------------------------------------------------------------
#define TS 16
__global__ void __launch_bounds__(256) k_U(const float* __restrict__ c_t,
                                           const float* __restrict__ W_a) {
    __shared__ float sc[TS][CC];
    const int bs0 = blockIdx.x * TS;
    const int tid = threadIdx.x;

    #pragma unroll
    for (int r = 0; r < TS; r++)
        sc[r][tid] = c_t[(size_t)(bs0 + r) * CC + tid];
    __syncthreads();

    float acc[TS];
    #pragma unroll
    for (int r = 0; r < TS; r++) acc[r] = 0.0f;

    float w0 = W_a[0 * CQ + tid];
    float w1 = W_a[1 * CQ + tid];
    float w2 = W_a[2 * CQ + tid];
    float w3 = W_a[3 * CQ + tid];

    for (int c0 = 0; c0 < CC; c0 += 4) {
        float n0 = 0.f, n1 = 0.f, n2 = 0.f, n3 = 0.f;
        if (c0 + 4 < CC) {
            n0 = W_a[(c0 + 4) * CQ + tid];
            n1 = W_a[(c0 + 5) * CQ + tid];
            n2 = W_a[(c0 + 6) * CQ + tid];
            n3 = W_a[(c0 + 7) * CQ + tid];
        }
        #pragma unroll
        for (int r = 0; r < TS; r++) {
            float4 s = *(const float4*)&sc[r][c0];         // broadcast LDS.128
            acc[r] += w0 * s.x + w1 * s.y + w2 * s.z + w3 * s.w;
        }
        w0 = n0; w1 = n1; w2 = n2; w3 = n3;
    }
    #pragma unroll
    for (int r = 0; r < TS; r++)
        g_U[(size_t)(bs0 + r) * CQ + tid] = acc[r];
}

// ---------------------------------------------------------------------------
// Kernel 2: one CTA per (b,s).  Fully float4 / LDG.128.
//   pass 1: a[k] = q1[k] . u      (warp-per-k, vectorized dot)
//   softmax + gaussian -> w[k]
//   pass 2: 4 k-groups x 64 channel-quads, SMEM cross-group reduce.
// ---------------------------------------------------------------------------
__global__ void __launch_bounds__(256) k2_attn(const float* __restrict__ q,
                                               float* __restrict__ out) {
    __shared__ float4 su4[CQ / 4];
    __shared__ int    srow[KK + 3];   // q row index, -1 == invalid
    __shared__ float  sa[KK + 3];
    __shared__ float  sw[KK + 3];
    __shared__ float4 spart[4][64];
    __shared__ float  sp;

    const int bs = blockIdx.x;
    const int b  = bs >> 11;          // SS = 2048
    const int tid = threadIdx.x;
    const int warp = tid >> 5, lane = tid & 31;

    ((float*)su4)[tid] = g_U[(size_t)bs * CQ + tid];
    if (tid == 0) sp = g_p[bs];
    __syncthreads();
    const float p = sp;

    // window indices (exactly torch semantics: trunc, clamp, mod S+1)
    if (tid < KK) {
        float raw = p + (float)(tid - DD) + 1.0f;
        int idx = (int)truncf(raw);
        if (idx < 0) idx = 0;
        if (idx > SS + 1) idx = SS + 1;
        idx = idx % (SS + 1);
        srow[tid] = idx - 1;
    }
    __syncthreads();

    const float* qb = q + (size_t)b * SS * CQ;

    // pass 1: scores (vectorized dot, warm L1 with the window)
    #pragma unroll 2
    for (int k = warp; k < KK; k += 8) {
        const int row = srow[k];
        float d = -INFINITY;
        if (row >= 0) {
            const float4* qr = (const float4*)(qb + (size_t)row * CQ);
            float4 a0 = qr[lane], a1 = qr[lane + 32];
            float4 u0 = su4[lane], u1 = su4[lane + 32];
            d = a0.x * u0.x + a0.y * u0.y + a0.z * u0.z + a0.w * u0.w
              + a1.x * u1.x + a1.y * u1.y + a1.z * u1.z + a1.w * u1.w;
            #pragma unroll
            for (int o = 16; o > 0; o >>= 1)
                d += __shfl_down_sync(0xffffffffu, d, o);
        }
        if (lane == 0) sa[k] = d;
    }
    __syncthreads();

    // softmax + gaussian decay (warp 0)
    if (warp == 0) {
        const float tp = truncf(p);
        float vals[4];
        float m = -INFINITY;
        #pragma unroll
        for (int t = 0; t < 4; t++) {
            int k = lane + 32 * t;
            vals[t] = (k < KK) ? sa[k] : -INFINITY;
            m = fmaxf(m, vals[t]);
        }
        #pragma unroll
        for (int o = 16; o > 0; o >>= 1)
            m = fmaxf(m, __shfl_xor_sync(0xffffffffu, m, o));
        float e[4];
        float ssum = 0.0f;
        #pragma unroll
        for (int t = 0; t < 4; t++) {
            e[t] = (vals[t] == -INFINITY) ? 0.0f : expf(vals[t] - m);
            ssum += e[t];
        }
        #pragma unroll
        for (int o = 16; o > 0; o >>= 1)
            ssum += __shfl_xor_sync(0xffffffffu, ssum, o);
        const float inv = 1.0f / ssum;
        #pragma unroll
        for (int t = 0; t < 4; t++) {
            int k = lane + 32 * t;
            if (k < KK) {
                float dd = ((float)(k - DD) + tp - p) * (1.0f / (float)DD);
                sw[k] = e[t] * inv * expf(-2.0f * dd * dd);
            }
        }
    }
    __syncthreads();

    // pass 2: weighted accumulation. thread = (k-group g, channel-quad c4).
    const int c4 = tid & 63;
    const int g  = tid >> 6;
    float4 acc = make_float4(0.f, 0.f, 0.f, 0.f);
    #pragma unroll 4
    for (int k = g; k < KK; k += 4) {
        int row = srow[k];
        const float w = sw[k];                 // 0 for invalid slots
        row = row < 0 ? 0 : row;               // branchless: garbage * 0 = 0
        const float4 v = *(const float4*)(qb + (size_t)row * CQ + 4 * c4);
        acc.x = fmaf(w, v.x, acc.x);
        acc.y = fmaf(w, v.y, acc.y);
        acc.z = fmaf(w, v.z, acc.z);
        acc.w = fmaf(w, v.w, acc.w);
    }
    spart[g][c4] = acc;
    __syncthreads();

    if (tid < 64) {
        float4 a0 = spart[0][tid], a1 = spart[1][tid];
        float4 a2 = spart[2][tid], a3 = spart[3][tid];
        float4 r;
        r.x = a0.x + a1.x + a2.x + a3.x;
        r.y = a0.y + a1.y + a2.y + a3.y;
        r.z = a0.z + a1.z + a2.z + a3.z;
        r.w = a0.w + a1.w + a2.w + a3.w;
        ((float4*)(out + (size_t)bs * CQ))[tid] = r;
    }
}

extern "C" void kernel_launch(void* const* d_in, const int* in_sizes, int n_in,
                              void* d_out, int out_size) {
    const float* q   = (const float*)d_in[0];
    const float* c_t = (const float*)d_in[1];
    const float* W_a = (const float*)d_in[2];
    const float* W_p = (const float*)d_in[3];
    const float* V_p = (const float*)d_in[4];
    float* out = (float*)d_out;

    const int pSmem = (PP * 257 + PR * CC) * (int)sizeof(float);   // ~135.6 KB
    cudaFuncSetAttribute(k_p, cudaFuncAttributeMaxDynamicSharedMemorySize, pSmem);

    k_p<<<(BB * SS) / PR, 256, pSmem>>>(c_t, W_p, V_p);
    k_U<<<(BB * SS) / TS, 256>>>(c_t, W_a);
    k2_attn<<<BB * SS, 256>>>(q, out);
}